// round 9
// baseline (speedup 1.0000x reference)
#include <cuda_runtime.h>
#include <cuda_bf16.h>
#include <cstdint>

// Problem dims
#define Bq 32
#define Tq 128
#define Hq 1024
#define Eq 1024
#define Vq 32000
#define Mq 4096   // B*T

// ---------------- scratch (static device memory; no allocs allowed) ----------
__device__ float g_xw[(size_t)Mq * Hq];            // pre-activations
__device__ float g_y [(size_t)Mq * Hq];            // layer outputs
__device__ float g_h0[Bq * Hq];                    // final hidden of layer 0
__device__ __align__(16) __nv_bfloat16 g_Ah[(size_t)Mq * Hq];    // A split hi
__device__ __align__(16) __nv_bfloat16 g_Al[(size_t)Mq * Hq];    // A split lo
__device__ __align__(16) __nv_bfloat16 g_Wh[(size_t)Vq * Hq];    // W split hi
__device__ __align__(16) __nv_bfloat16 g_Wl[(size_t)Vq * Hq];    // W split lo
__device__ unsigned g_bar_cnt;                     // global barrier state
__device__ unsigned g_bar_gen;

// ---------------- global barrier (sense-reversing) ---------------------------
__device__ __forceinline__ void gbar(unsigned nb) {
    __syncthreads();
    if (threadIdx.x == 0) {
        volatile unsigned* vgen = &g_bar_gen;
        unsigned gen = *vgen;
        __threadfence();
        if (atomicAdd(&g_bar_cnt, 1u) == nb - 1u) {
            atomicExch(&g_bar_cnt, 0u);
            __threadfence();
            atomicExch(&g_bar_gen, gen + 1u);
        } else {
            while (*vgen == gen) { __nanosleep(64); }
        }
    }
    __syncthreads();
}

// ---------------- PTX helpers (sm_80+ only: no 'a' features) ------------------
__device__ __forceinline__ uint32_t smem_u32(const void* p) {
    uint32_t a;
    asm("{ .reg .u64 t; cvta.to.shared.u64 t, %1; cvt.u32.u64 %0, t; }"
        : "=r"(a) : "l"(p));
    return a;
}

#define CP_ASYNC16(dst, src) \
    asm volatile("cp.async.cg.shared.global [%0], [%1], 16;" \
                 :: "r"(dst), "l"(src) : "memory")
#define CP_COMMIT()  asm volatile("cp.async.commit_group;" ::: "memory")
#define CP_WAIT1()   asm volatile("cp.async.wait_group 1;" ::: "memory")
#define CP_WAIT0()   asm volatile("cp.async.wait_group 0;" ::: "memory")

#define LDSM4(r, addr) \
    asm volatile("ldmatrix.sync.aligned.m8n8.x4.shared.b16 {%0,%1,%2,%3}, [%4];" \
                 : "=r"((r)[0]), "=r"((r)[1]), "=r"((r)[2]), "=r"((r)[3]) \
                 : "r"(addr))

#define MMA16816(c, a, b0v, b1v) \
    asm volatile("mma.sync.aligned.m16n8k16.row.col.f32.bf16.bf16.f32 " \
                 "{%0,%1,%2,%3}, {%4,%5,%6,%7}, {%8,%9}, {%0,%1,%2,%3};" \
                 : "+f"((c)[0]), "+f"((c)[1]), "+f"((c)[2]), "+f"((c)[3]) \
                 : "r"((a)[0]), "r"((a)[1]), "r"((a)[2]), "r"((a)[3]), \
                   "r"(b0v), "r"(b1v))

// ---------------- HMMA GEMM: C = A*W^T + bias, 3-term bf16 split --------------
// A ~ (Ah + Al) [M,1024], W ~ (Wh + Wl) [N,1024], row-major, K contiguous.
// C += Ah*Wh + Al*Wh + Ah*Wl   (fp32 accumulate; Al*Wl ~ 2^-18, dropped)
// Tile: 128x128, K-chunk 64, 256 threads (8 warps, warp tile 32x64),
// cp.async double-buffered, XOR-swizzled smem, ldmatrix fragments.
// MMA issue order: 3 groups of 16 INDEPENDENT MMAs (dep distance 16 per acc).
#define BM 128
#define BN 128
#define BK 64
#define NCH (Hq / BK)          // 16

// smem: 2 buffers x 4 tiles x (128 rows x 128 B) = 131072 B
#define TILE_B   16384
#define BUF_B    (4 * TILE_B)
#define SMEM_SZ  (2 * BUF_B)

__global__ __launch_bounds__(256)
void hmma_gemm(const __nv_bfloat16* __restrict__ Ah, const __nv_bfloat16* __restrict__ Al,
               const __nv_bfloat16* __restrict__ Wh, const __nv_bfloat16* __restrict__ Wl,
               const float* __restrict__ bias0, const float* __restrict__ bias1,
               float* __restrict__ C, int Nld)
{
    extern __shared__ __align__(128) char smem[];
    const uint32_t sb = smem_u32(smem);
    const int tid  = threadIdx.x;
    const int wid  = tid >> 5;
    const int lane = tid & 31;
    const int m0 = blockIdx.x * BM;
    const int n0 = blockIdx.y * BN;
    const int warp_m = (wid & 3) * 32;
    const int warp_n = (wid >> 2) * 64;

    const __nv_bfloat16* srcs[4] = {
        Ah + (size_t)m0 * Hq, Al + (size_t)m0 * Hq,
        Wh + (size_t)n0 * Hq, Wl + (size_t)n0 * Hq };

    auto prefetch = [&](int c) {
        const int buf = c & 1;
        const uint32_t dbase = sb + buf * BUF_B;
        const int k0e = c * BK;                       // element offset in K
        #pragma unroll
        for (int t2 = 0; t2 < 4; t2++) {
            #pragma unroll
            for (int it = 0; it < 4; it++) {
                int i = tid + it * 256;
                int row = i >> 3, u = i & 7;
                uint32_t dst = dbase + t2 * TILE_B + row * 128
                             + ((u ^ (row & 7)) << 4);
                const __nv_bfloat16* src = srcs[t2] + (size_t)row * Hq + k0e + u * 8;
                CP_ASYNC16(dst, src);
            }
        }
    };

    float acc[2][8][4];
    #pragma unroll
    for (int p = 0; p < 2; p++)
        #pragma unroll
        for (int q = 0; q < 8; q++)
            #pragma unroll
            for (int e = 0; e < 4; e++) acc[p][q][e] = 0.f;

    prefetch(0);
    CP_COMMIT();

    const int rA = warp_m + (lane & 15);
    const int rB = warp_n + (lane & 15);
    const int hsel = lane >> 4;

    for (int c = 0; c < NCH; c++) {
        if (c + 1 < NCH) { prefetch(c + 1); CP_COMMIT(); CP_WAIT1(); }
        else             { CP_WAIT0(); }
        __syncthreads();

        const uint32_t base = sb + (c & 1) * BUF_B;
        const uint32_t aAh = base;
        const uint32_t aAl = base + TILE_B;
        const uint32_t aWh = base + 2 * TILE_B;
        const uint32_t aWl = base + 3 * TILE_B;

        #pragma unroll
        for (int kk = 0; kk < 4; kk++) {
            // preload ALL fragments for this kk (12 LDSM, 48 regs)
            uint32_t fAh[2][4], fAl[2][4], fBh[4][4], fBl[4][4];
            #pragma unroll
            for (int p = 0; p < 2; p++) {
                int row = rA + p * 16;
                uint32_t off = row * 128 + (((2 * kk + hsel) ^ (row & 7)) << 4);
                LDSM4(fAh[p], aAh + off);
                LDSM4(fAl[p], aAl + off);
            }
            #pragma unroll
            for (int q = 0; q < 4; q++) {
                int row = rB + q * 16;
                uint32_t off = row * 128 + (((2 * kk + hsel) ^ (row & 7)) << 4);
                LDSM4(fBh[q], aWh + off);
                LDSM4(fBl[q], aWl + off);
            }
            // group 1: Ah*Wh — 16 independent MMAs
            #pragma unroll
            for (int q = 0; q < 4; q++)
                #pragma unroll
                for (int s = 0; s < 2; s++)
                    #pragma unroll
                    for (int p = 0; p < 2; p++)
                        MMA16816(acc[p][q * 2 + s], fAh[p], fBh[q][s], fBh[q][s + 2]);
            // group 2: Al*Wh — 16 independent MMAs
            #pragma unroll
            for (int q = 0; q < 4; q++)
                #pragma unroll
                for (int s = 0; s < 2; s++)
                    #pragma unroll
                    for (int p = 0; p < 2; p++)
                        MMA16816(acc[p][q * 2 + s], fAl[p], fBh[q][s], fBh[q][s + 2]);
            // group 3: Ah*Wl — 16 independent MMAs
            #pragma unroll
            for (int q = 0; q < 4; q++)
                #pragma unroll
                for (int s = 0; s < 2; s++)
                    #pragma unroll
                    for (int p = 0; p < 2; p++)
                        MMA16816(acc[p][q * 2 + s], fAh[p], fBl[q][s], fBl[q][s + 2]);
        }
        __syncthreads();
    }

    // epilogue: accum layout m16n8 -> thread (lane>>2, (lane&3)*2)
    const int r0 = m0 + warp_m + (lane >> 2);
    const int cb = n0 + warp_n + (lane & 3) * 2;
    #pragma unroll
    for (int p = 0; p < 2; p++) {
        #pragma unroll
        for (int q = 0; q < 8; q++) {
            int col = cb + q * 8;
            float b0v = __ldg(&bias0[col]);
            float b1v = __ldg(&bias0[col + 1]);
            if (bias1) { b0v += __ldg(&bias1[col]); b1v += __ldg(&bias1[col + 1]); }
            int row = r0 + p * 16;
            float2 v0 = make_float2(acc[p][q][0] + b0v, acc[p][q][1] + b1v);
            float2 v1 = make_float2(acc[p][q][2] + b0v, acc[p][q][3] + b1v);
            *(float2*)(C + (size_t)row * Nld + col)       = v0;
            *(float2*)(C + (size_t)(row + 8) * Nld + col) = v1;
        }
    }
}

// ---------------- bf16 split conversions -------------------------------------
__global__ void split_f32(const float* __restrict__ src,
                          __nv_bfloat16* __restrict__ hi,
                          __nv_bfloat16* __restrict__ lo, int n4)
{
    int i = blockIdx.x * blockDim.x + threadIdx.x;
    if (i >= n4) return;
    float4 v = ((const float4*)src)[i];
    float x[4] = {v.x, v.y, v.z, v.w};
    __nv_bfloat16 h[4], l[4];
    #pragma unroll
    for (int j = 0; j < 4; j++) {
        h[j] = __float2bfloat16(x[j]);
        l[j] = __float2bfloat16(x[j] - __bfloat162float(h[j]));
    }
    ((__nv_bfloat162*)hi)[2 * i]     = __halves2bfloat162(h[0], h[1]);
    ((__nv_bfloat162*)hi)[2 * i + 1] = __halves2bfloat162(h[2], h[3]);
    ((__nv_bfloat162*)lo)[2 * i]     = __halves2bfloat162(l[0], l[1]);
    ((__nv_bfloat162*)lo)[2 * i + 1] = __halves2bfloat162(l[2], l[3]);
}

// embedding gather + split (layer-0 A operand)
__global__ void gather_split(const float* __restrict__ emb, const int* __restrict__ idx,
                             __nv_bfloat16* __restrict__ hi, __nv_bfloat16* __restrict__ lo)
{
    int i = blockIdx.x * blockDim.x + threadIdx.x;   // Mq*256 threads
    int row = i >> 8, c4 = i & 255;
    int srow = idx[row];
    float4 v = ((const float4*)(emb + (size_t)srow * Eq))[c4];
    float x[4] = {v.x, v.y, v.z, v.w};
    __nv_bfloat16 h[4], l[4];
    #pragma unroll
    for (int j = 0; j < 4; j++) {
        h[j] = __float2bfloat16(x[j]);
        l[j] = __float2bfloat16(x[j] - __bfloat162float(h[j]));
    }
    ((__nv_bfloat162*)hi)[2 * i]     = __halves2bfloat162(h[0], h[1]);
    ((__nv_bfloat162*)hi)[2 * i + 1] = __halves2bfloat162(h[2], h[3]);
    ((__nv_bfloat162*)lo)[2 * i]     = __halves2bfloat162(l[0], l[1]);
    ((__nv_bfloat162*)lo)[2 * i + 1] = __halves2bfloat162(l[2], l[3]);
}

// ---------------- RNN recurrence (persistent, one global barrier per step) ---
__global__ __launch_bounds__(256)
void rnn_rec(const float* __restrict__ xw, const float* __restrict__ Whh,
             float* __restrict__ y)
{
    __shared__ __align__(16) float sh[8 * 1032];

    const int tid = threadIdx.x;
    const int bid = blockIdx.x;
    const unsigned nb = gridDim.x;
    const int jt = bid & 31;
    const int bg = bid >> 5;
    const int b0 = bg << 3;
    const int j  = (jt << 5) + (tid & 31);
    const int bl = tid >> 5;
    const int b  = b0 + bl;
    const float4* Wr = (const float4*)(Whh + ((size_t)j << 10));
    const float4* hr = (const float4*)(sh + bl * 1032);

    for (int t = 0; t < Tq; t++) {
        float acc = xw[(((size_t)(b * Tq + t)) << 10) + j];
        if (t > 0) {
            for (int i = tid; i < 2048; i += 256) {
                int sb2 = i >> 8, k4 = i & 255;
                float4 v = __ldcg((const float4*)(y +
                            (((size_t)((b0 + sb2) * Tq + (t - 1))) << 10)) + k4);
                *(float4*)(sh + sb2 * 1032 + (k4 << 2)) = v;
            }
            __syncthreads();
            float a0 = 0.f, a1 = 0.f, a2 = 0.f, a3 = 0.f;
            #pragma unroll 4
            for (int k4 = 0; k4 < 256; k4++) {
                float4 w = Wr[k4];
                float4 h = hr[k4];
                a0 += w.x * h.x; a1 += w.y * h.y;
                a2 += w.z * h.z; a3 += w.w * h.w;
            }
            acc += (a0 + a1) + (a2 + a3);
        }
        y[(((size_t)(b * Tq + t)) << 10) + j] = tanhf(acc);
        gbar(nb);
    }
}

// ---------------- small helpers ----------------------------------------------
__global__ void copy_h0_kernel(const float* __restrict__ y, float* __restrict__ h0) {
    int i = blockIdx.x * blockDim.x + threadIdx.x;
    int b = i >> 10, h = i & 1023;
    h0[i] = y[(((size_t)(b * Tq + (Tq - 1))) << 10) + h];
}

__global__ void finalize_kernel(const float* __restrict__ h0,
                                const float* __restrict__ y1,
                                const float* __restrict__ prob,
                                float* __restrict__ hid_out,
                                float* __restrict__ last_out)
{
    const int n1 = Bq * Hq;
    const int n2 = 2 * n1;
    const int total = n2 + Bq * Vq;
    for (int i = blockIdx.x * blockDim.x + threadIdx.x; i < total;
         i += gridDim.x * blockDim.x) {
        if (i < n1) {
            hid_out[i] = h0[i];
        } else if (i < n2) {
            int r = i - n1; int b = r >> 10, h = r & 1023;
            hid_out[i] = y1[(((size_t)(b * Tq + (Tq - 1))) << 10) + h];
        } else {
            int r = i - n2; int b = r / Vq, v = r % Vq;
            last_out[r] = prob[((size_t)(b * Tq + (Tq - 1))) * Vq + v];
        }
    }
}

// ---------------- launch -----------------------------------------------------
extern "C" void kernel_launch(void* const* d_in, const int* in_sizes, int n_in,
                              void* d_out, int out_size)
{
    (void)in_sizes; (void)n_in; (void)out_size;
    const int*   input_x = (const int*)  d_in[0];
    const float* emb   = (const float*)d_in[2];
    const float* W_ih0 = (const float*)d_in[3];
    const float* W_hh0 = (const float*)d_in[4];
    const float* b_ih0 = (const float*)d_in[5];
    const float* b_hh0 = (const float*)d_in[6];
    const float* W_ih1 = (const float*)d_in[7];
    const float* W_hh1 = (const float*)d_in[8];
    const float* b_ih1 = (const float*)d_in[9];
    const float* b_hh1 = (const float*)d_in[10];
    const float* W_out = (const float*)d_in[11];
    const float* b_out = (const float*)d_in[12];

    float* out      = (float*)d_out;
    float* out_prob = out;                                   // [4096, 32000]
    float* out_hid  = out + (size_t)Mq * Vq;                 // [2, 32, 1024]
    float* out_last = out_hid + (size_t)2 * Bq * Hq;         // [32, 32000]

    void* p;
    cudaGetSymbolAddress(&p, g_xw);  float* xw = (float*)p;
    cudaGetSymbolAddress(&p, g_y);   float* y  = (float*)p;
    cudaGetSymbolAddress(&p, g_h0);  float* h0 = (float*)p;
    cudaGetSymbolAddress(&p, g_Ah);  __nv_bfloat16* Ah = (__nv_bfloat16*)p;
    cudaGetSymbolAddress(&p, g_Al);  __nv_bfloat16* Al = (__nv_bfloat16*)p;
    cudaGetSymbolAddress(&p, g_Wh);  __nv_bfloat16* Wh = (__nv_bfloat16*)p;
    cudaGetSymbolAddress(&p, g_Wl);  __nv_bfloat16* Wl = (__nv_bfloat16*)p;

    cudaFuncSetAttribute(hmma_gemm, cudaFuncAttributeMaxDynamicSharedMemorySize, SMEM_SZ);

    const int nA4   = Mq * Hq / 4;     // 1,048,576
    const int nWih4 = Hq * Hq / 4;     //   262,144
    const int nWout4 = Vq * Hq / 4;    // 8,192,000

    dim3 gxw(Mq / BM, Hq / BN);        // (32, 8)
    dim3 gout(Mq / BM, Vq / BN);       // (32, 250)

    // layer 0: xw0 = emb[x] @ W_ih0^T + b_ih0 + b_hh0
    gather_split<<<Mq, 256>>>(emb, input_x, Ah, Al);
    split_f32<<<nWih4 / 256, 256>>>(W_ih0, Wh, Wl, nWih4);
    hmma_gemm<<<gxw, 256, SMEM_SZ>>>(Ah, Al, Wh, Wl, b_ih0, b_hh0, xw, Hq);
    rnn_rec<<<128, 256>>>(xw, W_hh0, y);

    // layer 1: xw1 = y0 @ W_ih1^T + b_ih1 + b_hh1
    split_f32<<<nA4 / 256, 256>>>(y, Ah, Al, nA4);
    split_f32<<<nWih4 / 256, 256>>>(W_ih1, Wh, Wl, nWih4);
    hmma_gemm<<<gxw, 256, SMEM_SZ>>>(Ah, Al, Wh, Wl, b_ih1, b_hh1, xw, Hq);
    copy_h0_kernel<<<128, 256>>>(y, h0);
    rnn_rec<<<128, 256>>>(xw, W_hh1, y);

    // output projection (dominant GEMM, tensor cores via mma.sync)
    split_f32<<<nA4 / 256, 256>>>(y, Ah, Al, nA4);
    split_f32<<<nWout4 / 256, 256>>>(W_out, Wh, Wl, nWout4);
    hmma_gemm<<<gout, 256, SMEM_SZ>>>(Ah, Al, Wh, Wl, b_out, nullptr, out_prob, Vq);

    // rnn_hidden + last_output (last_output == prob rows at t = T-1)
    finalize_kernel<<<2048, 256>>>(h0, y, out_prob, out_hid, out_last);
}

// round 11
// speedup vs baseline: 2.8752x; 2.8752x over previous
#include <cuda_runtime.h>
#include <cuda_bf16.h>
#include <cstdint>

// Problem dims
#define Bq 32
#define Tq 128
#define Hq 1024
#define Eq 1024
#define Vq 32000
#define Mq 4096   // B*T

// ---------------- scratch (static device memory; no allocs allowed) ----------
__device__ float g_xw[(size_t)Mq * Hq];            // pre-activations
__device__ float g_y [(size_t)Mq * Hq];            // layer outputs
__device__ float g_h0[Bq * Hq];                    // final hidden of layer 0
__device__ __align__(16) __nv_bfloat16 g_Ah[(size_t)Mq * Hq];    // A split hi
__device__ __align__(16) __nv_bfloat16 g_Al[(size_t)Mq * Hq];    // A split lo
__device__ __align__(16) __nv_bfloat16 g_Wh[(size_t)Vq * Hq];    // W split hi
__device__ __align__(16) __nv_bfloat16 g_Wl[(size_t)Vq * Hq];    // W split lo
__device__ unsigned g_bar_cnt;                     // global barrier state
__device__ unsigned g_bar_gen;

// ---------------- global barrier (sense-reversing) ---------------------------
__device__ __forceinline__ void gbar(unsigned nb) {
    __syncthreads();
    if (threadIdx.x == 0) {
        volatile unsigned* vgen = &g_bar_gen;
        unsigned gen = *vgen;
        __threadfence();
        if (atomicAdd(&g_bar_cnt, 1u) == nb - 1u) {
            atomicExch(&g_bar_cnt, 0u);
            __threadfence();
            atomicExch(&g_bar_gen, gen + 1u);
        } else {
            while (*vgen == gen) { __nanosleep(64); }
        }
    }
    __syncthreads();
}

// ---------------- packed f32x2 helpers ---------------------------------------
#define FFMA2(c, a, b) asm("fma.rn.f32x2 %0, %1, %2, %0;" : "+l"(c) : "l"(a), "l"(b))
#define UNPACK2(lo, hi, v) asm("mov.b64 {%0, %1}, %2;" : "=r"(lo), "=r"(hi) : "l"(v))

// ---------------- PTX helpers (sm_80+ only: no 'a' features) ------------------
__device__ __forceinline__ uint32_t smem_u32(const void* p) {
    uint32_t a;
    asm("{ .reg .u64 t; cvta.to.shared.u64 t, %1; cvt.u32.u64 %0, t; }"
        : "=r"(a) : "l"(p));
    return a;
}

#define CP_ASYNC16(dst, src) \
    asm volatile("cp.async.cg.shared.global [%0], [%1], 16;" \
                 :: "r"(dst), "l"(src) : "memory")
#define CP_COMMIT()  asm volatile("cp.async.commit_group;" ::: "memory")
#define CP_WAIT1()   asm volatile("cp.async.wait_group 1;" ::: "memory")
#define CP_WAIT0()   asm volatile("cp.async.wait_group 0;" ::: "memory")

#define LDSM4(r, addr) \
    asm volatile("ldmatrix.sync.aligned.m8n8.x4.shared.b16 {%0,%1,%2,%3}, [%4];" \
                 : "=r"((r)[0]), "=r"((r)[1]), "=r"((r)[2]), "=r"((r)[3]) \
                 : "r"(addr))

#define MMA16816(c, a, b0v, b1v) \
    asm volatile("mma.sync.aligned.m16n8k16.row.col.f32.bf16.bf16.f32 " \
                 "{%0,%1,%2,%3}, {%4,%5,%6,%7}, {%8,%9}, {%0,%1,%2,%3};" \
                 : "+f"((c)[0]), "+f"((c)[1]), "+f"((c)[2]), "+f"((c)[3]) \
                 : "r"((a)[0]), "r"((a)[1]), "r"((a)[2]), "r"((a)[3]), \
                   "r"(b0v), "r"(b1v))

// ---------------- HMMA GEMM: C = A*W^T + bias, 3-term bf16 split --------------
#define BM 128
#define BN 128
#define BK 64
#define NCH (Hq / BK)          // 16

#define TILE_B   16384
#define BUF_B    (4 * TILE_B)
#define SMEM_SZ  (2 * BUF_B)

__global__ __launch_bounds__(256)
void hmma_gemm(const __nv_bfloat16* __restrict__ Ah, const __nv_bfloat16* __restrict__ Al,
               const __nv_bfloat16* __restrict__ Wh, const __nv_bfloat16* __restrict__ Wl,
               const float* __restrict__ bias0, const float* __restrict__ bias1,
               float* __restrict__ C, int Nld)
{
    extern __shared__ __align__(128) char smem[];
    const uint32_t sb = smem_u32(smem);
    const int tid  = threadIdx.x;
    const int wid  = tid >> 5;
    const int lane = tid & 31;
    const int m0 = blockIdx.x * BM;
    const int n0 = blockIdx.y * BN;
    const int warp_m = (wid & 3) * 32;
    const int warp_n = (wid >> 2) * 64;

    const __nv_bfloat16* srcs[4] = {
        Ah + (size_t)m0 * Hq, Al + (size_t)m0 * Hq,
        Wh + (size_t)n0 * Hq, Wl + (size_t)n0 * Hq };

    auto prefetch = [&](int c) {
        const int buf = c & 1;
        const uint32_t dbase = sb + buf * BUF_B;
        const int k0e = c * BK;
        #pragma unroll
        for (int t2 = 0; t2 < 4; t2++) {
            #pragma unroll
            for (int it = 0; it < 4; it++) {
                int i = tid + it * 256;
                int row = i >> 3, u = i & 7;
                uint32_t dst = dbase + t2 * TILE_B + row * 128
                             + ((u ^ (row & 7)) << 4);
                const __nv_bfloat16* src = srcs[t2] + (size_t)row * Hq + k0e + u * 8;
                CP_ASYNC16(dst, src);
            }
        }
    };

    float acc[2][8][4];
    #pragma unroll
    for (int p = 0; p < 2; p++)
        #pragma unroll
        for (int q = 0; q < 8; q++)
            #pragma unroll
            for (int e = 0; e < 4; e++) acc[p][q][e] = 0.f;

    prefetch(0);
    CP_COMMIT();

    const int rA = warp_m + (lane & 15);
    const int rB = warp_n + (lane & 15);
    const int hsel = lane >> 4;

    for (int c = 0; c < NCH; c++) {
        if (c + 1 < NCH) { prefetch(c + 1); CP_COMMIT(); CP_WAIT1(); }
        else             { CP_WAIT0(); }
        __syncthreads();

        const uint32_t base = sb + (c & 1) * BUF_B;
        const uint32_t aAh = base;
        const uint32_t aAl = base + TILE_B;
        const uint32_t aWh = base + 2 * TILE_B;
        const uint32_t aWl = base + 3 * TILE_B;

        #pragma unroll
        for (int kk = 0; kk < 4; kk++) {
            uint32_t fAh[2][4], fAl[2][4], fBh[4][4], fBl[4][4];
            #pragma unroll
            for (int p = 0; p < 2; p++) {
                int row = rA + p * 16;
                uint32_t off = row * 128 + (((2 * kk + hsel) ^ (row & 7)) << 4);
                LDSM4(fAh[p], aAh + off);
                LDSM4(fAl[p], aAl + off);
            }
            #pragma unroll
            for (int q = 0; q < 4; q++) {
                int row = rB + q * 16;
                uint32_t off = row * 128 + (((2 * kk + hsel) ^ (row & 7)) << 4);
                LDSM4(fBh[q], aWh + off);
                LDSM4(fBl[q], aWl + off);
            }
            #pragma unroll
            for (int q = 0; q < 4; q++)
                #pragma unroll
                for (int s = 0; s < 2; s++)
                    #pragma unroll
                    for (int p = 0; p < 2; p++)
                        MMA16816(acc[p][q * 2 + s], fAh[p], fBh[q][s], fBh[q][s + 2]);
            #pragma unroll
            for (int q = 0; q < 4; q++)
                #pragma unroll
                for (int s = 0; s < 2; s++)
                    #pragma unroll
                    for (int p = 0; p < 2; p++)
                        MMA16816(acc[p][q * 2 + s], fAl[p], fBh[q][s], fBh[q][s + 2]);
            #pragma unroll
            for (int q = 0; q < 4; q++)
                #pragma unroll
                for (int s = 0; s < 2; s++)
                    #pragma unroll
                    for (int p = 0; p < 2; p++)
                        MMA16816(acc[p][q * 2 + s], fAh[p], fBl[q][s], fBl[q][s + 2]);
        }
        __syncthreads();
    }

    const int r0 = m0 + warp_m + (lane >> 2);
    const int cb = n0 + warp_n + (lane & 3) * 2;
    #pragma unroll
    for (int p = 0; p < 2; p++) {
        #pragma unroll
        for (int q = 0; q < 8; q++) {
            int col = cb + q * 8;
            float b0v = __ldg(&bias0[col]);
            float b1v = __ldg(&bias0[col + 1]);
            if (bias1) { b0v += __ldg(&bias1[col]); b1v += __ldg(&bias1[col + 1]); }
            int row = r0 + p * 16;
            float2 v0 = make_float2(acc[p][q][0] + b0v, acc[p][q][1] + b1v);
            float2 v1 = make_float2(acc[p][q][2] + b0v, acc[p][q][3] + b1v);
            *(float2*)(C + (size_t)row * Nld + col)       = v0;
            *(float2*)(C + (size_t)(row + 8) * Nld + col) = v1;
        }
    }
}

// ---------------- bf16 split conversions -------------------------------------
__global__ void split_f32(const float* __restrict__ src,
                          __nv_bfloat16* __restrict__ hi,
                          __nv_bfloat16* __restrict__ lo, int n4)
{
    int i = blockIdx.x * blockDim.x + threadIdx.x;
    if (i >= n4) return;
    float4 v = ((const float4*)src)[i];
    float x[4] = {v.x, v.y, v.z, v.w};
    __nv_bfloat16 h[4], l[4];
    #pragma unroll
    for (int j = 0; j < 4; j++) {
        h[j] = __float2bfloat16(x[j]);
        l[j] = __float2bfloat16(x[j] - __bfloat162float(h[j]));
    }
    ((__nv_bfloat162*)hi)[2 * i]     = __halves2bfloat162(h[0], h[1]);
    ((__nv_bfloat162*)hi)[2 * i + 1] = __halves2bfloat162(h[2], h[3]);
    ((__nv_bfloat162*)lo)[2 * i]     = __halves2bfloat162(l[0], l[1]);
    ((__nv_bfloat162*)lo)[2 * i + 1] = __halves2bfloat162(l[2], l[3]);
}

// embedding gather + split (layer-0 A operand)
__global__ void gather_split(const float* __restrict__ emb, const int* __restrict__ idx,
                             __nv_bfloat16* __restrict__ hi, __nv_bfloat16* __restrict__ lo)
{
    int i = blockIdx.x * blockDim.x + threadIdx.x;   // Mq*256 threads
    int row = i >> 8, c4 = i & 255;
    int srow = idx[row];
    float4 v = ((const float4*)(emb + (size_t)srow * Eq))[c4];
    float x[4] = {v.x, v.y, v.z, v.w};
    __nv_bfloat16 h[4], l[4];
    #pragma unroll
    for (int j = 0; j < 4; j++) {
        h[j] = __float2bfloat16(x[j]);
        l[j] = __float2bfloat16(x[j] - __bfloat162float(h[j]));
    }
    ((__nv_bfloat162*)hi)[2 * i]     = __halves2bfloat162(h[0], h[1]);
    ((__nv_bfloat162*)hi)[2 * i + 1] = __halves2bfloat162(h[2], h[3]);
    ((__nv_bfloat162*)lo)[2 * i]     = __halves2bfloat162(l[0], l[1]);
    ((__nv_bfloat162*)lo)[2 * i + 1] = __halves2bfloat162(l[2], l[3]);
}

// ---------------- RNN recurrence v2: W_hh resident in registers --------------
// 128 blocks (32 j-tiles x 4 b-groups), 256 threads.
// Thread (jj, s): jj = tid>>3 (j within tile), s = tid&7 (k-slice of 128).
// Owns W_hh[j][128s .. 128s+128) in 128 registers for the whole t-loop.
// Per step: stage prev hidden rows (8 b x 1024) into bank-swizzled smem,
// compute 8 partial dots (f32x2 FMA, 16 indep accumulators), shfl-reduce
// over the 8 k-slices, lane s finalizes batch b0+s.
__global__ __launch_bounds__(256, 1)
void rnn_rec(const float* __restrict__ xw, const float* __restrict__ Whh,
             float* __restrict__ y)
{
    __shared__ __align__(16) float sh[8][1032];

    const int tid = threadIdx.x;
    const int bid = blockIdx.x;
    const unsigned nb = gridDim.x;
    const int jt = bid & 31;
    const int bg = bid >> 5;
    const int b0 = bg << 3;
    const int jj = tid >> 3;            // 0..31
    const int s  = tid & 7;             // 0..7 k-slice
    const int j  = (jt << 5) + jj;
    const int bme = b0 + s;             // batch this thread finalizes

    // W slice into registers (persists across the whole recurrence)
    ulonglong2 wreg[32];
    {
        const ulonglong2* wsrc =
            (const ulonglong2*)(Whh + ((size_t)j << 10) + (s << 7));
        #pragma unroll
        for (int k4 = 0; k4 < 32; k4++) wreg[k4] = wsrc[k4];
    }

    const float* xb = xw + (((size_t)(bme * Tq)) << 10) + j;
    float* yb       = y  + (((size_t)(bme * Tq)) << 10) + j;
    const int sbase = s << 7;           // s*128 floats

    for (int t = 0; t < Tq; t++) {
        float xwv = __ldg(xb + ((size_t)t << 10));   // issue early
        float val = 0.f;
        if (t > 0) {
            // stage prev hidden rows, bank-swizzled: logical (sk, kl) float4
            // stored at sk*128 + ((kl+sk)&31)*4
            #pragma unroll
            for (int it = 0; it < 8; it++) {
                int i = tid + it * 256;
                int sb2 = i >> 8, kg = i & 255;
                int sk = kg >> 5, kl = kg & 31;
                float4 v = __ldcg((const float4*)(y +
                            (((size_t)((b0 + sb2) * Tq + (t - 1))) << 10)) + kg);
                *(float4*)(&sh[sb2][0] + (sk << 7) + (((kl + sk) & 31) << 2)) = v;
            }
            __syncthreads();

            unsigned long long a0[8], a1[8];
            #pragma unroll
            for (int b = 0; b < 8; b++) { a0[b] = 0ull; a1[b] = 0ull; }

            #pragma unroll
            for (int k4 = 0; k4 < 32; k4++) {
                const float* hp = &sh[0][0] + sbase + (((k4 + s) & 31) << 2);
                ulonglong2 w2 = wreg[k4];
                #pragma unroll
                for (int b = 0; b < 8; b++) {
                    ulonglong2 h2 = *(const ulonglong2*)(hp + b * 1032);
                    FFMA2(a0[b], h2.x, w2.x);
                    FFMA2(a1[b], h2.y, w2.y);
                }
            }

            float part[8];
            #pragma unroll
            for (int b = 0; b < 8; b++) {
                unsigned l0, h0v, l1, h1v;
                UNPACK2(l0, h0v, a0[b]);
                UNPACK2(l1, h1v, a1[b]);
                part[b] = (__uint_as_float(l0) + __uint_as_float(h0v))
                        + (__uint_as_float(l1) + __uint_as_float(h1v));
            }
            // reduce over the 8 k-slices (lanes grouped by 8)
            #pragma unroll
            for (int d = 1; d < 8; d <<= 1)
                #pragma unroll
                for (int b = 0; b < 8; b++)
                    part[b] += __shfl_xor_sync(0xffffffffu, part[b], d, 8);
            val = part[0];
            #pragma unroll
            for (int b = 1; b < 8; b++) if (s == b) val = part[b];
        }
        yb[(size_t)t << 10] = tanhf(xwv + val);
        gbar(nb);
    }
}

// ---------------- small helpers ----------------------------------------------
__global__ void copy_h0_kernel(const float* __restrict__ y, float* __restrict__ h0) {
    int i = blockIdx.x * blockDim.x + threadIdx.x;
    int b = i >> 10, h = i & 1023;
    h0[i] = y[(((size_t)(b * Tq + (Tq - 1))) << 10) + h];
}

__global__ void finalize_kernel(const float* __restrict__ h0,
                                const float* __restrict__ y1,
                                const float* __restrict__ prob,
                                float* __restrict__ hid_out,
                                float* __restrict__ last_out)
{
    const int n1 = Bq * Hq;
    const int n2 = 2 * n1;
    const int total = n2 + Bq * Vq;
    for (int i = blockIdx.x * blockDim.x + threadIdx.x; i < total;
         i += gridDim.x * blockDim.x) {
        if (i < n1) {
            hid_out[i] = h0[i];
        } else if (i < n2) {
            int r = i - n1; int b = r >> 10, h = r & 1023;
            hid_out[i] = y1[(((size_t)(b * Tq + (Tq - 1))) << 10) + h];
        } else {
            int r = i - n2; int b = r / Vq, v = r % Vq;
            last_out[r] = prob[((size_t)(b * Tq + (Tq - 1))) * Vq + v];
        }
    }
}

// ---------------- launch -----------------------------------------------------
extern "C" void kernel_launch(void* const* d_in, const int* in_sizes, int n_in,
                              void* d_out, int out_size)
{
    (void)in_sizes; (void)n_in; (void)out_size;
    const int*   input_x = (const int*)  d_in[0];
    const float* emb   = (const float*)d_in[2];
    const float* W_ih0 = (const float*)d_in[3];
    const float* W_hh0 = (const float*)d_in[4];
    const float* b_ih0 = (const float*)d_in[5];
    const float* b_hh0 = (const float*)d_in[6];
    const float* W_ih1 = (const float*)d_in[7];
    const float* W_hh1 = (const float*)d_in[8];
    const float* b_ih1 = (const float*)d_in[9];
    const float* b_hh1 = (const float*)d_in[10];
    const float* W_out = (const float*)d_in[11];
    const float* b_out = (const float*)d_in[12];

    float* out      = (float*)d_out;
    float* out_prob = out;                                   // [4096, 32000]
    float* out_hid  = out + (size_t)Mq * Vq;                 // [2, 32, 1024]
    float* out_last = out_hid + (size_t)2 * Bq * Hq;         // [32, 32000]

    void* p;
    cudaGetSymbolAddress(&p, g_xw);  float* xw = (float*)p;
    cudaGetSymbolAddress(&p, g_y);   float* y  = (float*)p;
    cudaGetSymbolAddress(&p, g_h0);  float* h0 = (float*)p;
    cudaGetSymbolAddress(&p, g_Ah);  __nv_bfloat16* Ah = (__nv_bfloat16*)p;
    cudaGetSymbolAddress(&p, g_Al);  __nv_bfloat16* Al = (__nv_bfloat16*)p;
    cudaGetSymbolAddress(&p, g_Wh);  __nv_bfloat16* Wh = (__nv_bfloat16*)p;
    cudaGetSymbolAddress(&p, g_Wl);  __nv_bfloat16* Wl = (__nv_bfloat16*)p;

    cudaFuncSetAttribute(hmma_gemm, cudaFuncAttributeMaxDynamicSharedMemorySize, SMEM_SZ);

    const int nA4   = Mq * Hq / 4;     // 1,048,576
    const int nWih4 = Hq * Hq / 4;     //   262,144
    const int nWout4 = Vq * Hq / 4;    // 8,192,000

    dim3 gxw(Mq / BM, Hq / BN);        // (32, 8)
    dim3 gout(Mq / BM, Vq / BN);       // (32, 250)

    // layer 0: xw0 = emb[x] @ W_ih0^T + b_ih0 + b_hh0
    gather_split<<<Mq, 256>>>(emb, input_x, Ah, Al);
    split_f32<<<nWih4 / 256, 256>>>(W_ih0, Wh, Wl, nWih4);
    hmma_gemm<<<gxw, 256, SMEM_SZ>>>(Ah, Al, Wh, Wl, b_ih0, b_hh0, xw, Hq);
    rnn_rec<<<128, 256>>>(xw, W_hh0, y);

    // layer 1: xw1 = y0 @ W_ih1^T + b_ih1 + b_hh1
    split_f32<<<nA4 / 256, 256>>>(y, Ah, Al, nA4);
    split_f32<<<nWih4 / 256, 256>>>(W_ih1, Wh, Wl, nWih4);
    hmma_gemm<<<gxw, 256, SMEM_SZ>>>(Ah, Al, Wh, Wl, b_ih1, b_hh1, xw, Hq);
    copy_h0_kernel<<<128, 256>>>(y, h0);
    rnn_rec<<<128, 256>>>(xw, W_hh1, y);

    // output projection (dominant GEMM, tensor cores via mma.sync)
    split_f32<<<nA4 / 256, 256>>>(y, Ah, Al, nA4);
    split_f32<<<nWout4 / 256, 256>>>(W_out, Wh, Wl, nWout4);
    hmma_gemm<<<gout, 256, SMEM_SZ>>>(Ah, Al, Wh, Wl, b_out, nullptr, out_prob, Vq);

    // rnn_hidden + last_output (last_output == prob rows at t = T-1)
    finalize_kernel<<<2048, 256>>>(h0, y, out_prob, out_hid, out_last);
}

// round 12
// speedup vs baseline: 2.9779x; 1.0357x over previous
#include <cuda_runtime.h>
#include <cuda_bf16.h>
#include <cstdint>

// Problem dims
#define Bq 32
#define Tq 128
#define Hq 1024
#define Eq 1024
#define Vq 32000
#define Mq 4096   // B*T

// ---------------- scratch (static device memory; no allocs allowed) ----------
__device__ float g_xw[(size_t)Mq * Hq];            // pre-activations
__device__ float g_y [(size_t)Mq * Hq];            // layer outputs
__device__ float g_h0[Bq * Hq];                    // final hidden of layer 0
__device__ __align__(16) __nv_bfloat16 g_Ah[(size_t)Mq * Hq];    // A split hi
__device__ __align__(16) __nv_bfloat16 g_Al[(size_t)Mq * Hq];    // A split lo
__device__ __align__(16) __nv_bfloat16 g_Wh[(size_t)Vq * Hq];    // W split hi
__device__ __align__(16) __nv_bfloat16 g_Wl[(size_t)Vq * Hq];    // W split lo
// per-(layer, batch-group, step) arrival counters: [2][4][Tq]
__device__ unsigned g_cnt[2 * 4 * Tq];

// ---------------- packed f32x2 helpers ---------------------------------------
#define FFMA2(c, a, b) asm("fma.rn.f32x2 %0, %1, %2, %0;" : "+l"(c) : "l"(a), "l"(b))
#define UNPACK2(lo, hi, v) asm("mov.b64 {%0, %1}, %2;" : "=r"(lo), "=r"(hi) : "l"(v))

// ---------------- PTX helpers (sm_80+ only: no 'a' features) ------------------
__device__ __forceinline__ uint32_t smem_u32(const void* p) {
    uint32_t a;
    asm("{ .reg .u64 t; cvta.to.shared.u64 t, %1; cvt.u32.u64 %0, t; }"
        : "=r"(a) : "l"(p));
    return a;
}

#define CP_ASYNC16(dst, src) \
    asm volatile("cp.async.cg.shared.global [%0], [%1], 16;" \
                 :: "r"(dst), "l"(src) : "memory")
#define CP_COMMIT()  asm volatile("cp.async.commit_group;" ::: "memory")
#define CP_WAIT1()   asm volatile("cp.async.wait_group 1;" ::: "memory")
#define CP_WAIT0()   asm volatile("cp.async.wait_group 0;" ::: "memory")

#define LDSM4(r, addr) \
    asm volatile("ldmatrix.sync.aligned.m8n8.x4.shared.b16 {%0,%1,%2,%3}, [%4];" \
                 : "=r"((r)[0]), "=r"((r)[1]), "=r"((r)[2]), "=r"((r)[3]) \
                 : "r"(addr))

#define MMA16816(c, a, b0v, b1v) \
    asm volatile("mma.sync.aligned.m16n8k16.row.col.f32.bf16.bf16.f32 " \
                 "{%0,%1,%2,%3}, {%4,%5,%6,%7}, {%8,%9}, {%0,%1,%2,%3};" \
                 : "+f"((c)[0]), "+f"((c)[1]), "+f"((c)[2]), "+f"((c)[3]) \
                 : "r"((a)[0]), "r"((a)[1]), "r"((a)[2]), "r"((a)[3]), \
                   "r"(b0v), "r"(b1v))

// ---------------- HMMA GEMM: C = A*W^T + bias, 3-term bf16 split --------------
#define BM 128
#define BN 128
#define BK 64
#define NCH (Hq / BK)          // 16

#define TILE_B   16384
#define BUF_B    (4 * TILE_B)
#define SMEM_SZ  (2 * BUF_B)

__global__ __launch_bounds__(256)
void hmma_gemm(const __nv_bfloat16* __restrict__ Ah, const __nv_bfloat16* __restrict__ Al,
               const __nv_bfloat16* __restrict__ Wh, const __nv_bfloat16* __restrict__ Wl,
               const float* __restrict__ bias0, const float* __restrict__ bias1,
               float* __restrict__ C, int Nld)
{
    extern __shared__ __align__(128) char smem[];
    const uint32_t sb = smem_u32(smem);
    const int tid  = threadIdx.x;
    const int wid  = tid >> 5;
    const int lane = tid & 31;
    const int m0 = blockIdx.x * BM;
    const int n0 = blockIdx.y * BN;
    const int warp_m = (wid & 3) * 32;
    const int warp_n = (wid >> 2) * 64;

    const __nv_bfloat16* srcs[4] = {
        Ah + (size_t)m0 * Hq, Al + (size_t)m0 * Hq,
        Wh + (size_t)n0 * Hq, Wl + (size_t)n0 * Hq };

    auto prefetch = [&](int c) {
        const int buf = c & 1;
        const uint32_t dbase = sb + buf * BUF_B;
        const int k0e = c * BK;
        #pragma unroll
        for (int t2 = 0; t2 < 4; t2++) {
            #pragma unroll
            for (int it = 0; it < 4; it++) {
                int i = tid + it * 256;
                int row = i >> 3, u = i & 7;
                uint32_t dst = dbase + t2 * TILE_B + row * 128
                             + ((u ^ (row & 7)) << 4);
                const __nv_bfloat16* src = srcs[t2] + (size_t)row * Hq + k0e + u * 8;
                CP_ASYNC16(dst, src);
            }
        }
    };

    float acc[2][8][4];
    #pragma unroll
    for (int p = 0; p < 2; p++)
        #pragma unroll
        for (int q = 0; q < 8; q++)
            #pragma unroll
            for (int e = 0; e < 4; e++) acc[p][q][e] = 0.f;

    prefetch(0);
    CP_COMMIT();

    const int rA = warp_m + (lane & 15);
    const int rB = warp_n + (lane & 15);
    const int hsel = lane >> 4;

    for (int c = 0; c < NCH; c++) {
        if (c + 1 < NCH) { prefetch(c + 1); CP_COMMIT(); CP_WAIT1(); }
        else             { CP_WAIT0(); }
        __syncthreads();

        const uint32_t base = sb + (c & 1) * BUF_B;
        const uint32_t aAh = base;
        const uint32_t aAl = base + TILE_B;
        const uint32_t aWh = base + 2 * TILE_B;
        const uint32_t aWl = base + 3 * TILE_B;

        #pragma unroll
        for (int kk = 0; kk < 4; kk++) {
            uint32_t fAh[2][4], fAl[2][4], fBh[4][4], fBl[4][4];
            #pragma unroll
            for (int p = 0; p < 2; p++) {
                int row = rA + p * 16;
                uint32_t off = row * 128 + (((2 * kk + hsel) ^ (row & 7)) << 4);
                LDSM4(fAh[p], aAh + off);
                LDSM4(fAl[p], aAl + off);
            }
            #pragma unroll
            for (int q = 0; q < 4; q++) {
                int row = rB + q * 16;
                uint32_t off = row * 128 + (((2 * kk + hsel) ^ (row & 7)) << 4);
                LDSM4(fBh[q], aWh + off);
                LDSM4(fBl[q], aWl + off);
            }
            #pragma unroll
            for (int q = 0; q < 4; q++)
                #pragma unroll
                for (int s = 0; s < 2; s++)
                    #pragma unroll
                    for (int p = 0; p < 2; p++)
                        MMA16816(acc[p][q * 2 + s], fAh[p], fBh[q][s], fBh[q][s + 2]);
            #pragma unroll
            for (int q = 0; q < 4; q++)
                #pragma unroll
                for (int s = 0; s < 2; s++)
                    #pragma unroll
                    for (int p = 0; p < 2; p++)
                        MMA16816(acc[p][q * 2 + s], fAl[p], fBh[q][s], fBh[q][s + 2]);
            #pragma unroll
            for (int q = 0; q < 4; q++)
                #pragma unroll
                for (int s = 0; s < 2; s++)
                    #pragma unroll
                    for (int p = 0; p < 2; p++)
                        MMA16816(acc[p][q * 2 + s], fAh[p], fBl[q][s], fBl[q][s + 2]);
        }
        __syncthreads();
    }

    const int r0 = m0 + warp_m + (lane >> 2);
    const int cb = n0 + warp_n + (lane & 3) * 2;
    #pragma unroll
    for (int p = 0; p < 2; p++) {
        #pragma unroll
        for (int q = 0; q < 8; q++) {
            int col = cb + q * 8;
            float b0v = __ldg(&bias0[col]);
            float b1v = __ldg(&bias0[col + 1]);
            if (bias1) { b0v += __ldg(&bias1[col]); b1v += __ldg(&bias1[col + 1]); }
            int row = r0 + p * 16;
            float2 v0 = make_float2(acc[p][q][0] + b0v, acc[p][q][1] + b1v);
            float2 v1 = make_float2(acc[p][q][2] + b0v, acc[p][q][3] + b1v);
            *(float2*)(C + (size_t)row * Nld + col)       = v0;
            *(float2*)(C + (size_t)(row + 8) * Nld + col) = v1;
        }
    }
}

// ---------------- bf16 split conversions -------------------------------------
__global__ void split_f32(const float* __restrict__ src,
                          __nv_bfloat16* __restrict__ hi,
                          __nv_bfloat16* __restrict__ lo, int n4)
{
    int i = blockIdx.x * blockDim.x + threadIdx.x;
    if (i >= n4) return;
    float4 v = ((const float4*)src)[i];
    float x[4] = {v.x, v.y, v.z, v.w};
    __nv_bfloat16 h[4], l[4];
    #pragma unroll
    for (int j = 0; j < 4; j++) {
        h[j] = __float2bfloat16(x[j]);
        l[j] = __float2bfloat16(x[j] - __bfloat162float(h[j]));
    }
    ((__nv_bfloat162*)hi)[2 * i]     = __halves2bfloat162(h[0], h[1]);
    ((__nv_bfloat162*)hi)[2 * i + 1] = __halves2bfloat162(h[2], h[3]);
    ((__nv_bfloat162*)lo)[2 * i]     = __halves2bfloat162(l[0], l[1]);
    ((__nv_bfloat162*)lo)[2 * i + 1] = __halves2bfloat162(l[2], l[3]);
}

// embedding gather + split (layer-0 A operand)
__global__ void gather_split(const float* __restrict__ emb, const int* __restrict__ idx,
                             __nv_bfloat16* __restrict__ hi, __nv_bfloat16* __restrict__ lo)
{
    int i = blockIdx.x * blockDim.x + threadIdx.x;   // Mq*256 threads
    int row = i >> 8, c4 = i & 255;
    int srow = idx[row];
    float4 v = ((const float4*)(emb + (size_t)srow * Eq))[c4];
    float x[4] = {v.x, v.y, v.z, v.w};
    __nv_bfloat16 h[4], l[4];
    #pragma unroll
    for (int j = 0; j < 4; j++) {
        h[j] = __float2bfloat16(x[j]);
        l[j] = __float2bfloat16(x[j] - __bfloat162float(h[j]));
    }
    ((__nv_bfloat162*)hi)[2 * i]     = __halves2bfloat162(h[0], h[1]);
    ((__nv_bfloat162*)hi)[2 * i + 1] = __halves2bfloat162(h[2], h[3]);
    ((__nv_bfloat162*)lo)[2 * i]     = __halves2bfloat162(l[0], l[1]);
    ((__nv_bfloat162*)lo)[2 * i + 1] = __halves2bfloat162(l[2], l[3]);
}

// ---------------- counter reset (per kernel_launch call) ----------------------
__global__ void zero_cnt_kernel() {
    int i = blockIdx.x * blockDim.x + threadIdx.x;
    if (i < 2 * 4 * Tq) g_cnt[i] = 0u;
}

// ---------------- RNN recurrence v3: reg-resident W + per-group flags --------
// 128 blocks (32 j-tiles x 4 b-groups), 256 threads.
// Thread (jj, s): jj = tid>>3, s = tid&7; owns W_hh[j][128s..128s+128) in regs.
// Sync: per batch-group (32 blocks), per-step monotone counters. A block
// arrives on cnt[bg][t] after its y writes; waits cnt[bg][t-1]==32 before
// staging. Groups are fully independent (no global coupling).
__global__ __launch_bounds__(256, 1)
void rnn_rec(const float* __restrict__ xw, const float* __restrict__ Whh,
             float* __restrict__ y, unsigned* __restrict__ cnt)
{
    __shared__ __align__(16) float sh[8][1032];

    const int tid = threadIdx.x;
    const int bid = blockIdx.x;
    const int jt = bid & 31;
    const int bg = bid >> 5;
    const int b0 = bg << 3;
    const int jj = tid >> 3;            // 0..31
    const int s  = tid & 7;             // 0..7 k-slice
    const int j  = (jt << 5) + jj;
    const int bme = b0 + s;             // batch this thread finalizes

    unsigned* mycnt = cnt + bg * Tq;    // this group's per-step counters

    // W slice into registers (persists across the whole recurrence)
    ulonglong2 wreg[32];
    {
        const ulonglong2* wsrc =
            (const ulonglong2*)(Whh + ((size_t)j << 10) + (s << 7));
        #pragma unroll
        for (int k4 = 0; k4 < 32; k4++) wreg[k4] = wsrc[k4];
    }

    const float* xb = xw + (((size_t)(bme * Tq)) << 10) + j;
    float* yb       = y  + (((size_t)(bme * Tq)) << 10) + j;
    const int sbase = s << 7;           // s*128 floats

    for (int t = 0; t < Tq; t++) {
        float xwv = __ldg(xb + ((size_t)t << 10));   // issue early
        float val = 0.f;
        if (t > 0) {
            // wait for this batch-group's previous step (single waiter + bar)
            if (tid == 0) {
                volatile unsigned* c = mycnt + (t - 1);
                while (*c != 32u) { }
                __threadfence();
            }
            __syncthreads();

            // stage prev hidden rows, bank-swizzled
            #pragma unroll
            for (int it = 0; it < 8; it++) {
                int i = tid + it * 256;
                int sb2 = i >> 8, kg = i & 255;
                int sk = kg >> 5, kl = kg & 31;
                float4 v = __ldcg((const float4*)(y +
                            (((size_t)((b0 + sb2) * Tq + (t - 1))) << 10)) + kg);
                *(float4*)(&sh[sb2][0] + (sk << 7) + (((kl + sk) & 31) << 2)) = v;
            }
            __syncthreads();

            unsigned long long a0[8], a1[8];
            #pragma unroll
            for (int b = 0; b < 8; b++) { a0[b] = 0ull; a1[b] = 0ull; }

            #pragma unroll
            for (int k4 = 0; k4 < 32; k4++) {
                const float* hp = &sh[0][0] + sbase + (((k4 + s) & 31) << 2);
                ulonglong2 w2 = wreg[k4];
                #pragma unroll
                for (int b = 0; b < 8; b++) {
                    ulonglong2 h2 = *(const ulonglong2*)(hp + b * 1032);
                    FFMA2(a0[b], h2.x, w2.x);
                    FFMA2(a1[b], h2.y, w2.y);
                }
            }

            float part[8];
            #pragma unroll
            for (int b = 0; b < 8; b++) {
                unsigned l0, h0v, l1, h1v;
                UNPACK2(l0, h0v, a0[b]);
                UNPACK2(l1, h1v, a1[b]);
                part[b] = (__uint_as_float(l0) + __uint_as_float(h0v))
                        + (__uint_as_float(l1) + __uint_as_float(h1v));
            }
            // reduce over the 8 k-slices (lanes grouped by 8)
            #pragma unroll
            for (int d = 1; d < 8; d <<= 1)
                #pragma unroll
                for (int b = 0; b < 8; b++)
                    part[b] += __shfl_xor_sync(0xffffffffu, part[b], d, 8);
            val = part[0];
            #pragma unroll
            for (int b = 1; b < 8; b++) if (s == b) val = part[b];
        }
        yb[(size_t)t << 10] = tanhf(xwv + val);

        // publish this step for the group
        __syncthreads();
        if (tid == 0) {
            __threadfence();
            atomicAdd(mycnt + t, 1u);
        }
    }
}

// ---------------- small helpers ----------------------------------------------
__global__ void copy_h0_kernel(const float* __restrict__ y, float* __restrict__ h0) {
    int i = blockIdx.x * blockDim.x + threadIdx.x;
    int b = i >> 10, h = i & 1023;
    h0[i] = y[(((size_t)(b * Tq + (Tq - 1))) << 10) + h];
}

__global__ void finalize_kernel(const float* __restrict__ h0,
                                const float* __restrict__ y1,
                                const float* __restrict__ prob,
                                float* __restrict__ hid_out,
                                float* __restrict__ last_out)
{
    const int n1 = Bq * Hq;
    const int n2 = 2 * n1;
    const int total = n2 + Bq * Vq;
    for (int i = blockIdx.x * blockDim.x + threadIdx.x; i < total;
         i += gridDim.x * blockDim.x) {
        if (i < n1) {
            hid_out[i] = h0[i];
        } else if (i < n2) {
            int r = i - n1; int b = r >> 10, h = r & 1023;
            hid_out[i] = y1[(((size_t)(b * Tq + (Tq - 1))) << 10) + h];
        } else {
            int r = i - n2; int b = r / Vq, v = r % Vq;
            last_out[r] = prob[((size_t)(b * Tq + (Tq - 1))) * Vq + v];
        }
    }
}

// ---------------- launch -----------------------------------------------------
extern "C" void kernel_launch(void* const* d_in, const int* in_sizes, int n_in,
                              void* d_out, int out_size)
{
    (void)in_sizes; (void)n_in; (void)out_size;
    const int*   input_x = (const int*)  d_in[0];
    const float* emb   = (const float*)d_in[2];
    const float* W_ih0 = (const float*)d_in[3];
    const float* W_hh0 = (const float*)d_in[4];
    const float* b_ih0 = (const float*)d_in[5];
    const float* b_hh0 = (const float*)d_in[6];
    const float* W_ih1 = (const float*)d_in[7];
    const float* W_hh1 = (const float*)d_in[8];
    const float* b_ih1 = (const float*)d_in[9];
    const float* b_hh1 = (const float*)d_in[10];
    const float* W_out = (const float*)d_in[11];
    const float* b_out = (const float*)d_in[12];

    float* out      = (float*)d_out;
    float* out_prob = out;                                   // [4096, 32000]
    float* out_hid  = out + (size_t)Mq * Vq;                 // [2, 32, 1024]
    float* out_last = out_hid + (size_t)2 * Bq * Hq;         // [32, 32000]

    void* p;
    cudaGetSymbolAddress(&p, g_xw);  float* xw = (float*)p;
    cudaGetSymbolAddress(&p, g_y);   float* y  = (float*)p;
    cudaGetSymbolAddress(&p, g_h0);  float* h0 = (float*)p;
    cudaGetSymbolAddress(&p, g_Ah);  __nv_bfloat16* Ah = (__nv_bfloat16*)p;
    cudaGetSymbolAddress(&p, g_Al);  __nv_bfloat16* Al = (__nv_bfloat16*)p;
    cudaGetSymbolAddress(&p, g_Wh);  __nv_bfloat16* Wh = (__nv_bfloat16*)p;
    cudaGetSymbolAddress(&p, g_Wl);  __nv_bfloat16* Wl = (__nv_bfloat16*)p;
    cudaGetSymbolAddress(&p, g_cnt); unsigned* cnt = (unsigned*)p;

    cudaFuncSetAttribute(hmma_gemm, cudaFuncAttributeMaxDynamicSharedMemorySize, SMEM_SZ);

    const int nA4   = Mq * Hq / 4;     // 1,048,576
    const int nWih4 = Hq * Hq / 4;     //   262,144
    const int nWout4 = Vq * Hq / 4;    // 8,192,000

    dim3 gxw(Mq / BM, Hq / BN);        // (32, 8)
    dim3 gout(Mq / BM, Vq / BN);       // (32, 250)

    // reset per-step sync counters (both layers)
    zero_cnt_kernel<<<4, 256>>>();

    // layer 0: xw0 = emb[x] @ W_ih0^T + b_ih0 + b_hh0
    gather_split<<<Mq, 256>>>(emb, input_x, Ah, Al);
    split_f32<<<nWih4 / 256, 256>>>(W_ih0, Wh, Wl, nWih4);
    hmma_gemm<<<gxw, 256, SMEM_SZ>>>(Ah, Al, Wh, Wl, b_ih0, b_hh0, xw, Hq);
    rnn_rec<<<128, 256>>>(xw, W_hh0, y, cnt);

    // layer 1: xw1 = y0 @ W_ih1^T + b_ih1 + b_hh1
    split_f32<<<nA4 / 256, 256>>>(y, Ah, Al, nA4);
    split_f32<<<nWih4 / 256, 256>>>(W_ih1, Wh, Wl, nWih4);
    hmma_gemm<<<gxw, 256, SMEM_SZ>>>(Ah, Al, Wh, Wl, b_ih1, b_hh1, xw, Hq);
    copy_h0_kernel<<<128, 256>>>(y, h0);
    rnn_rec<<<128, 256>>>(xw, W_hh1, y, cnt + 4 * Tq);

    // output projection (dominant GEMM, tensor cores via mma.sync)
    split_f32<<<nA4 / 256, 256>>>(y, Ah, Al, nA4);
    split_f32<<<nWout4 / 256, 256>>>(W_out, Wh, Wl, nWout4);
    hmma_gemm<<<gout, 256, SMEM_SZ>>>(Ah, Al, Wh, Wl, b_out, nullptr, out_prob, Vq);

    // rnn_hidden + last_output (last_output == prob rows at t = T-1)
    finalize_kernel<<<2048, 256>>>(h0, y, out_prob, out_hid, out_last);
}

// round 17
// speedup vs baseline: 3.4094x; 1.1449x over previous
#include <cuda_runtime.h>
#include <cuda_bf16.h>
#include <cstdint>

// Problem dims
#define Bq 32
#define Tq 128
#define Hq 1024
#define Eq 1024
#define Vq 32000
#define Mq 4096   // B*T

// ---------------- scratch (static device memory; no allocs allowed) ----------
__device__ float g_xw[(size_t)Mq * Hq];            // pre-activations
__device__ float g_y [(size_t)Mq * Hq];            // layer outputs
__device__ float g_h0[Bq * Hq];                    // final hidden of layer 0
__device__ __align__(16) __nv_bfloat16 g_Ah[(size_t)Mq * Hq];    // A split hi
__device__ __align__(16) __nv_bfloat16 g_Al[(size_t)Mq * Hq];    // A split lo
__device__ __align__(16) __nv_bfloat16 g_Wh[(size_t)Vq * Hq];    // W split hi
__device__ __align__(16) __nv_bfloat16 g_Wl[(size_t)Vq * Hq];    // W split lo
// per-(layer, batch-group, step) arrival counters: [2][4][Tq]
__device__ unsigned g_cnt[2 * 4 * Tq];

// ---------------- packed f32x2 helpers ---------------------------------------
#define FFMA2(c, a, b) asm("fma.rn.f32x2 %0, %1, %2, %0;" : "+l"(c) : "l"(a), "l"(b))
#define UNPACK2(lo, hi, v) asm("mov.b64 {%0, %1}, %2;" : "=r"(lo), "=r"(hi) : "l"(v))

// ---------------- PTX helpers (sm_80+ only: no 'a' features) ------------------
__device__ __forceinline__ uint32_t smem_u32(const void* p) {
    uint32_t a;
    asm("{ .reg .u64 t; cvta.to.shared.u64 t, %1; cvt.u32.u64 %0, t; }"
        : "=r"(a) : "l"(p));
    return a;
}

#define CP_ASYNC16(dst, src) \
    asm volatile("cp.async.cg.shared.global [%0], [%1], 16;" \
                 :: "r"(dst), "l"(src) : "memory")
#define CP_COMMIT()  asm volatile("cp.async.commit_group;" ::: "memory")
#define CP_WAIT1()   asm volatile("cp.async.wait_group 1;" ::: "memory")
#define CP_WAIT0()   asm volatile("cp.async.wait_group 0;" ::: "memory")

#define LDSM4(r, addr) \
    asm volatile("ldmatrix.sync.aligned.m8n8.x4.shared.b16 {%0,%1,%2,%3}, [%4];" \
                 : "=r"((r)[0]), "=r"((r)[1]), "=r"((r)[2]), "=r"((r)[3]) \
                 : "r"(addr))

#define MMA16816(c, a, b0v, b1v) \
    asm volatile("mma.sync.aligned.m16n8k16.row.col.f32.bf16.bf16.f32 " \
                 "{%0,%1,%2,%3}, {%4,%5,%6,%7}, {%8,%9}, {%0,%1,%2,%3};" \
                 : "+f"((c)[0]), "+f"((c)[1]), "+f"((c)[2]), "+f"((c)[3]) \
                 : "r"((a)[0]), "r"((a)[1]), "r"((a)[2]), "r"((a)[3]), \
                   "r"(b0v), "r"(b1v))

// ---------------- HMMA GEMM: C = A*W^T + bias, 3-term bf16 split --------------
// BK=32 chunks, 64 KB smem total -> 2 CTAs/SM for latency hiding.
#define BM 128
#define BN 128
#define BK 32
#define NCH (Hq / BK)          // 32

#define TILE_B   (128 * 64)    // 8192 B (128 rows x 32 bf16)
#define BUF_B    (4 * TILE_B)  // 32768
#define SMEM_SZ  (2 * BUF_B)   // 65536

__global__ __launch_bounds__(256, 2)
void hmma_gemm(const __nv_bfloat16* __restrict__ Ah, const __nv_bfloat16* __restrict__ Al,
               const __nv_bfloat16* __restrict__ Wh, const __nv_bfloat16* __restrict__ Wl,
               const float* __restrict__ bias0, const float* __restrict__ bias1,
               float* __restrict__ C, int Nld)
{
    extern __shared__ __align__(128) char smem[];
    const uint32_t sb = smem_u32(smem);
    const int tid  = threadIdx.x;
    const int wid  = tid >> 5;
    const int lane = tid & 31;
    const int m0 = blockIdx.x * BM;
    const int n0 = blockIdx.y * BN;
    const int warp_m = (wid & 3) * 32;
    const int warp_n = (wid >> 2) * 64;

    const __nv_bfloat16* srcs[4] = {
        Ah + (size_t)m0 * Hq, Al + (size_t)m0 * Hq,
        Wh + (size_t)n0 * Hq, Wl + (size_t)n0 * Hq };

    auto prefetch = [&](int c) {
        const int buf = c & 1;
        const uint32_t dbase = sb + buf * BUF_B;
        const int k0e = c * BK;
        #pragma unroll
        for (int t2 = 0; t2 < 4; t2++) {
            #pragma unroll
            for (int it = 0; it < 2; it++) {
                int i = tid + it * 256;             // 0..511
                int row = i >> 2, u = i & 3;
                uint32_t dst = dbase + t2 * TILE_B + row * 64
                             + ((u ^ (row & 3)) << 4);
                const __nv_bfloat16* src = srcs[t2] + (size_t)row * Hq + k0e + u * 8;
                CP_ASYNC16(dst, src);
            }
        }
    };

    float acc[2][8][4];
    #pragma unroll
    for (int p = 0; p < 2; p++)
        #pragma unroll
        for (int q = 0; q < 8; q++)
            #pragma unroll
            for (int e = 0; e < 4; e++) acc[p][q][e] = 0.f;

    prefetch(0);
    CP_COMMIT();

    const int rA = warp_m + (lane & 15);
    const int rB = warp_n + (lane & 15);
    const int hsel = lane >> 4;

    for (int c = 0; c < NCH; c++) {
        if (c + 1 < NCH) { prefetch(c + 1); CP_COMMIT(); CP_WAIT1(); }
        else             { CP_WAIT0(); }
        __syncthreads();

        const uint32_t base = sb + (c & 1) * BUF_B;
        const uint32_t aAh = base;
        const uint32_t aAl = base + TILE_B;
        const uint32_t aWh = base + 2 * TILE_B;
        const uint32_t aWl = base + 3 * TILE_B;

        #pragma unroll
        for (int kk = 0; kk < 2; kk++) {
            uint32_t fAh[2][4], fAl[2][4], fBh[4][4], fBl[4][4];
            #pragma unroll
            for (int p = 0; p < 2; p++) {
                int row = rA + p * 16;
                uint32_t off = row * 64 + (((2 * kk + hsel) ^ (row & 3)) << 4);
                LDSM4(fAh[p], aAh + off);
                LDSM4(fAl[p], aAl + off);
            }
            #pragma unroll
            for (int q = 0; q < 4; q++) {
                int row = rB + q * 16;
                uint32_t off = row * 64 + (((2 * kk + hsel) ^ (row & 3)) << 4);
                LDSM4(fBh[q], aWh + off);
                LDSM4(fBl[q], aWl + off);
            }
            #pragma unroll
            for (int q = 0; q < 4; q++)
                #pragma unroll
                for (int s = 0; s < 2; s++)
                    #pragma unroll
                    for (int p = 0; p < 2; p++)
                        MMA16816(acc[p][q * 2 + s], fAh[p], fBh[q][s], fBh[q][s + 2]);
            #pragma unroll
            for (int q = 0; q < 4; q++)
                #pragma unroll
                for (int s = 0; s < 2; s++)
                    #pragma unroll
                    for (int p = 0; p < 2; p++)
                        MMA16816(acc[p][q * 2 + s], fAl[p], fBh[q][s], fBh[q][s + 2]);
            #pragma unroll
            for (int q = 0; q < 4; q++)
                #pragma unroll
                for (int s = 0; s < 2; s++)
                    #pragma unroll
                    for (int p = 0; p < 2; p++)
                        MMA16816(acc[p][q * 2 + s], fAh[p], fBl[q][s], fBl[q][s + 2]);
        }
        __syncthreads();
    }

    const int r0 = m0 + warp_m + (lane >> 2);
    const int cb = n0 + warp_n + (lane & 3) * 2;
    #pragma unroll
    for (int p = 0; p < 2; p++) {
        #pragma unroll
        for (int q = 0; q < 8; q++) {
            int col = cb + q * 8;
            float b0v = __ldg(&bias0[col]);
            float b1v = __ldg(&bias0[col + 1]);
            if (bias1) { b0v += __ldg(&bias1[col]); b1v += __ldg(&bias1[col + 1]); }
            int row = r0 + p * 16;
            float2 v0 = make_float2(acc[p][q][0] + b0v, acc[p][q][1] + b1v);
            float2 v1 = make_float2(acc[p][q][2] + b0v, acc[p][q][3] + b1v);
            *(float2*)(C + (size_t)row * Nld + col)       = v0;
            *(float2*)(C + (size_t)(row + 8) * Nld + col) = v1;
        }
    }
}

// ---------------- bf16 split conversions -------------------------------------
__global__ void split_f32(const float* __restrict__ src,
                          __nv_bfloat16* __restrict__ hi,
                          __nv_bfloat16* __restrict__ lo, int n4)
{
    int i = blockIdx.x * blockDim.x + threadIdx.x;
    if (i >= n4) return;
    float4 v = ((const float4*)src)[i];
    float x[4] = {v.x, v.y, v.z, v.w};
    __nv_bfloat16 h[4], l[4];
    #pragma unroll
    for (int j = 0; j < 4; j++) {
        h[j] = __float2bfloat16(x[j]);
        l[j] = __float2bfloat16(x[j] - __bfloat162float(h[j]));
    }
    ((__nv_bfloat162*)hi)[2 * i]     = __halves2bfloat162(h[0], h[1]);
    ((__nv_bfloat162*)hi)[2 * i + 1] = __halves2bfloat162(h[2], h[3]);
    ((__nv_bfloat162*)lo)[2 * i]     = __halves2bfloat162(l[0], l[1]);
    ((__nv_bfloat162*)lo)[2 * i + 1] = __halves2bfloat162(l[2], l[3]);
}

// embedding gather + split (layer-0 A operand)
__global__ void gather_split(const float* __restrict__ emb, const int* __restrict__ idx,
                             __nv_bfloat16* __restrict__ hi, __nv_bfloat16* __restrict__ lo)
{
    int i = blockIdx.x * blockDim.x + threadIdx.x;   // Mq*256 threads
    int row = i >> 8, c4 = i & 255;
    int srow = idx[row];
    float4 v = ((const float4*)(emb + (size_t)srow * Eq))[c4];
    float x[4] = {v.x, v.y, v.z, v.w};
    __nv_bfloat16 h[4], l[4];
    #pragma unroll
    for (int j = 0; j < 4; j++) {
        h[j] = __float2bfloat16(x[j]);
        l[j] = __float2bfloat16(x[j] - __bfloat162float(h[j]));
    }
    ((__nv_bfloat162*)hi)[2 * i]     = __halves2bfloat162(h[0], h[1]);
    ((__nv_bfloat162*)hi)[2 * i + 1] = __halves2bfloat162(h[2], h[3]);
    ((__nv_bfloat162*)lo)[2 * i]     = __halves2bfloat162(l[0], l[1]);
    ((__nv_bfloat162*)lo)[2 * i + 1] = __halves2bfloat162(l[2], l[3]);
}

// ---------------- counter reset (per kernel_launch call) ----------------------
__global__ void zero_cnt_kernel() {
    int i = blockIdx.x * blockDim.x + threadIdx.x;
    if (i < 2 * 4 * Tq) g_cnt[i] = 0u;
}

// ---------------- RNN recurrence v4: broadcast-LDS layout ---------------------
// 128 blocks (32 j-tiles x 4 b-groups), 256 threads = 8 warps.
// Warp w = k-slice s (owns k in [128w, 128w+128)); lane = jj (j within tile).
// Every lane of a warp reads the SAME h word -> pure LDS broadcast (N=1).
// W_hh[j][slice] resident in 128 regs. Cross-warp (over s) reduction via
// padded smem. Sync: per batch-group per-step monotone counters.
__global__ __launch_bounds__(256, 1)
void rnn_rec(const float* __restrict__ xw, const float* __restrict__ Whh,
             float* __restrict__ y, unsigned* __restrict__ cnt)
{
    __shared__ __align__(16) float sh[8 * 1028];   // 8 batch rows, 16B-aligned stride
    __shared__ float red[8 * 288];                 // [s][jj*9 + b] padded

    const int tid  = threadIdx.x;
    const int bid  = blockIdx.x;
    const int jt   = bid & 31;
    const int bg   = bid >> 5;
    const int b0   = bg << 3;
    const int s    = tid >> 5;          // warp id = k-slice
    const int lane = tid & 31;          // jj
    const int j    = (jt << 5) + lane;

    unsigned* mycnt = cnt + bg * Tq;

    // W slice into registers (persists across the whole recurrence)
    ulonglong2 wreg[32];
    {
        const ulonglong2* wsrc =
            (const ulonglong2*)(Whh + ((size_t)j << 10) + (s << 7));
        #pragma unroll
        for (int k4 = 0; k4 < 32; k4++) wreg[k4] = wsrc[k4];
    }

    // this thread finalizes (batch b0+s, hidden j) — lane-coalesced I/O
    const int bf = b0 + s;
    const float* xb = xw + (((size_t)(bf * Tq)) << 10) + j;
    float* yb       = y  + (((size_t)(bf * Tq)) << 10) + j;

    for (int t = 0; t < Tq; t++) {
        float xwv = __ldg(xb + ((size_t)t << 10));   // issue early
        float val = 0.f;
        if (t > 0) {
            // wait for this batch-group's previous step
            if (tid == 0) {
                volatile unsigned* c = mycnt + (t - 1);
                while (*c != 32u) { }
                __threadfence();
            }
            __syncthreads();

            // stage prev hidden rows (plain layout; reads are broadcast)
            #pragma unroll
            for (int it = 0; it < 8; it++) {
                int i = tid + it * 256;
                int sb2 = i >> 8, kg = i & 255;
                float4 v = __ldcg((const float4*)(y +
                            (((size_t)((b0 + sb2) * Tq + (t - 1))) << 10)) + kg);
                *(float4*)(sh + sb2 * 1028 + (kg << 2)) = v;
            }
            __syncthreads();

            unsigned long long a0[8], a1[8];
            #pragma unroll
            for (int b = 0; b < 8; b++) { a0[b] = 0ull; a1[b] = 0ull; }

            const float* hp0 = sh + (s << 7);
            #pragma unroll
            for (int k4 = 0; k4 < 32; k4++) {
                ulonglong2 w2 = wreg[k4];
                #pragma unroll
                for (int b = 0; b < 8; b++) {
                    ulonglong2 h2 =
                        *(const ulonglong2*)(hp0 + b * 1028 + (k4 << 2));
                    FFMA2(a0[b], h2.x, w2.x);
                    FFMA2(a1[b], h2.y, w2.y);
                }
            }

            // per-slice partials -> padded smem
            #pragma unroll
            for (int b = 0; b < 8; b++) {
                unsigned l0, h0v, l1, h1v;
                UNPACK2(l0, h0v, a0[b]);
                UNPACK2(l1, h1v, a1[b]);
                red[s * 288 + lane * 9 + b] =
                    (__uint_as_float(l0) + __uint_as_float(h0v))
                  + (__uint_as_float(l1) + __uint_as_float(h1v));
            }
            __syncthreads();

            // sum over the 8 slices for (jj=lane, b=s)
            #pragma unroll
            for (int ss = 0; ss < 8; ss++)
                val += red[ss * 288 + lane * 9 + s];
        }
        yb[(size_t)t << 10] = tanhf(xwv + val);

        // publish this step for the group
        __syncthreads();
        if (tid == 0) {
            __threadfence();
            atomicAdd(mycnt + t, 1u);
        }
    }
}

// ---------------- small helpers ----------------------------------------------
__global__ void copy_h0_kernel(const float* __restrict__ y, float* __restrict__ h0) {
    int i = blockIdx.x * blockDim.x + threadIdx.x;
    int b = i >> 10, h = i & 1023;
    h0[i] = y[(((size_t)(b * Tq + (Tq - 1))) << 10) + h];
}

__global__ void finalize_kernel(const float* __restrict__ h0,
                                const float* __restrict__ y1,
                                const float* __restrict__ prob,
                                float* __restrict__ hid_out,
                                float* __restrict__ last_out)
{
    const int n1 = Bq * Hq;
    const int n2 = 2 * n1;
    const int total = n2 + Bq * Vq;
    for (int i = blockIdx.x * blockDim.x + threadIdx.x; i < total;
         i += gridDim.x * blockDim.x) {
        if (i < n1) {
            hid_out[i] = h0[i];
        } else if (i < n2) {
            int r = i - n1; int b = r >> 10, h = r & 1023;
            hid_out[i] = y1[(((size_t)(b * Tq + (Tq - 1))) << 10) + h];
        } else {
            int r = i - n2; int b = r / Vq, v = r % Vq;
            last_out[r] = prob[((size_t)(b * Tq + (Tq - 1))) * Vq + v];
        }
    }
}

// ---------------- launch -----------------------------------------------------
extern "C" void kernel_launch(void* const* d_in, const int* in_sizes, int n_in,
                              void* d_out, int out_size)
{
    (void)in_sizes; (void)n_in; (void)out_size;
    const int*   input_x = (const int*)  d_in[0];
    const float* emb   = (const float*)d_in[2];
    const float* W_ih0 = (const float*)d_in[3];
    const float* W_hh0 = (const float*)d_in[4];
    const float* b_ih0 = (const float*)d_in[5];
    const float* b_hh0 = (const float*)d_in[6];
    const float* W_ih1 = (const float*)d_in[7];
    const float* W_hh1 = (const float*)d_in[8];
    const float* b_ih1 = (const float*)d_in[9];
    const float* b_hh1 = (const float*)d_in[10];
    const float* W_out = (const float*)d_in[11];
    const float* b_out = (const float*)d_in[12];

    float* out      = (float*)d_out;
    float* out_prob = out;                                   // [4096, 32000]
    float* out_hid  = out + (size_t)Mq * Vq;                 // [2, 32, 1024]
    float* out_last = out_hid + (size_t)2 * Bq * Hq;         // [32, 32000]

    void* p;
    cudaGetSymbolAddress(&p, g_xw);  float* xw = (float*)p;
    cudaGetSymbolAddress(&p, g_y);   float* y  = (float*)p;
    cudaGetSymbolAddress(&p, g_h0);  float* h0 = (float*)p;
    cudaGetSymbolAddress(&p, g_Ah);  __nv_bfloat16* Ah = (__nv_bfloat16*)p;
    cudaGetSymbolAddress(&p, g_Al);  __nv_bfloat16* Al = (__nv_bfloat16*)p;
    cudaGetSymbolAddress(&p, g_Wh);  __nv_bfloat16* Wh = (__nv_bfloat16*)p;
    cudaGetSymbolAddress(&p, g_Wl);  __nv_bfloat16* Wl = (__nv_bfloat16*)p;
    cudaGetSymbolAddress(&p, g_cnt); unsigned* cnt = (unsigned*)p;

    cudaFuncSetAttribute(hmma_gemm, cudaFuncAttributeMaxDynamicSharedMemorySize, SMEM_SZ);

    const int nA4   = Mq * Hq / 4;     // 1,048,576
    const int nWih4 = Hq * Hq / 4;     //   262,144
    const int nWout4 = Vq * Hq / 4;    // 8,192,000

    dim3 gxw(Mq / BM, Hq / BN);        // (32, 8)
    dim3 gout(Mq / BM, Vq / BN);       // (32, 250)

    // reset per-step sync counters (both layers)
    zero_cnt_kernel<<<4, 256>>>();

    // layer 0: xw0 = emb[x] @ W_ih0^T + b_ih0 + b_hh0
    gather_split<<<Mq, 256>>>(emb, input_x, Ah, Al);
    split_f32<<<nWih4 / 256, 256>>>(W_ih0, Wh, Wl, nWih4);
    hmma_gemm<<<gxw, 256, SMEM_SZ>>>(Ah, Al, Wh, Wl, b_ih0, b_hh0, xw, Hq);
    rnn_rec<<<128, 256>>>(xw, W_hh0, y, cnt);

    // layer 1: xw1 = y0 @ W_ih1^T + b_ih1 + b_hh1
    split_f32<<<nA4 / 256, 256>>>(y, Ah, Al, nA4);
    split_f32<<<nWih4 / 256, 256>>>(W_ih1, Wh, Wl, nWih4);
    hmma_gemm<<<gxw, 256, SMEM_SZ>>>(Ah, Al, Wh, Wl, b_ih1, b_hh1, xw, Hq);
    copy_h0_kernel<<<128, 256>>>(y, h0);
    rnn_rec<<<128, 256>>>(xw, W_hh1, y, cnt + 4 * Tq);

    // output projection (dominant GEMM, tensor cores via mma.sync)
    split_f32<<<nA4 / 256, 256>>>(y, Ah, Al, nA4);
    split_f32<<<nWout4 / 256, 256>>>(W_out, Wh, Wl, nWout4);
    hmma_gemm<<<gout, 256, SMEM_SZ>>>(Ah, Al, Wh, Wl, b_out, nullptr, out_prob, Vq);

    // rnn_hidden + last_output (last_output == prob rows at t = T-1)
    finalize_kernel<<<2048, 256>>>(h0, y, out_prob, out_hid, out_last);
}